// round 17
// baseline (speedup 1.0000x reference)
#include <cuda_runtime.h>

// obj_coord [B,Q,4] f32, sub_coord [B,Q,4] f32, img_size [B,2] i32, mask (shape only)
// output [2,B,Q,H,W] f32: 1.0 OUTSIDE the inclusive box, 0.0 inside.
#define BB 64
#define QQ 300
#define HM 40
#define WM 40

// One block per output plane (s,b,q). Warp 0 builds two 40-float row templates
// in smem (inside-row pattern, all-ones); 400 worker threads each emit one
// float4 via LDS.128 -> STG.128 with only a row-range predicate in between.
__global__ __launch_bounds__(416) void part_mask_kernel(
    const float* __restrict__ obj_coord,
    const float* __restrict__ sub_coord,
    const int* __restrict__ img_size,
    float* __restrict__ out)
{
    __shared__ float4 tpl[20];   // [0..9] = inside-row pattern, [10..19] = all ones
    __shared__ int2   sy;        // (y1, y2)

    const int plane = blockIdx.x;            // plane = s*B*Q + b*Q + q
    const int t = threadIdx.x;

    if (t < 32) {
        const int q  = plane % QQ;
        const int sb = plane / QQ;
        const int b  = sb % BB;
        const int s  = sb / BB;

        const float* coord = (s == 0 ? obj_coord : sub_coord) + (size_t)(b * QQ + q) * 4;
        const float4 c = *reinterpret_cast<const float4*>(coord);   // cx, cy, w, h

        const float shf = (float)img_size[2 * b + 0];   // img_h
        const float swf = (float)img_size[2 * b + 1];   // img_w

        // Match JAX's unfused f32 evaluation exactly ( /32 == *0.03125 exactly ).
        const float hw = __fmul_rn(0.5f, c.z);
        const float hh = __fmul_rn(0.5f, c.w);
        const int x1 = (int)floorf(__fmul_rn(__fmul_rn(__fsub_rn(c.x, hw), swf), 0.03125f));
        const int y1 = (int)floorf(__fmul_rn(__fmul_rn(__fsub_rn(c.y, hh), shf), 0.03125f));
        const int x2 = min((int)floorf(__fmul_rn(__fmul_rn(__fadd_rn(c.x, hw), swf), 0.03125f)), WM - 1);
        const int y2 = min((int)floorf(__fmul_rn(__fmul_rn(__fadd_rn(c.y, hh), shf), 0.03125f)), HM - 1);

        if (t < 10) {
            const int wb = t * 4;
            float4 r;
            r.x = ((wb + 0 < x1) | (wb + 0 > x2)) ? 1.0f : 0.0f;
            r.y = ((wb + 1 < x1) | (wb + 1 > x2)) ? 1.0f : 0.0f;
            r.z = ((wb + 2 < x1) | (wb + 2 > x2)) ? 1.0f : 0.0f;
            r.w = ((wb + 3 < x1) | (wb + 3 > x2)) ? 1.0f : 0.0f;
            tpl[t]      = r;
            tpl[t + 10] = make_float4(1.0f, 1.0f, 1.0f, 1.0f);
        }
        if (t == 0) sy = make_int2(y1, y2);
    }
    __syncthreads();

    if (t < 400) {
        const int h = t / 10;          // magic-mul, no real division
        const int c = t - h * 10;
        const int2 y = sy;
        const bool rout = (h < y.x) | (h > y.y);
        const float4 v = tpl[(rout ? 10 : 0) + c];
        reinterpret_cast<float4*>(out + (size_t)plane * (HM * WM))[t] = v;
    }
}

extern "C" void kernel_launch(void* const* d_in, const int* in_sizes, int n_in,
                              void* d_out, int out_size) {
    const float* obj = (const float*)d_in[0];
    const float* sub = (const float*)d_in[1];
    const int*   img = (const int*)d_in[2];
    float* out = (float*)d_out;

    part_mask_kernel<<<2 * BB * QQ, 416>>>(obj, sub, img, out);
}